// round 8
// baseline (speedup 1.0000x reference)
#include <cuda_runtime.h>
#include <cuda_bf16.h>
#include <math.h>
#include <stdint.h>

#define BB 8
#define NN 4096
#define CC 512
#define DD 64
#define LOG2E 1.4426950408889634f

// Scratch (allocation-free: __device__ globals)
__device__ __nv_bfloat16 g_f[BB * NN * DD];
__device__ __nv_bfloat16 g_g[BB * NN * DD];
__device__ __nv_bfloat16 g_h[BB * NN * DD];
__device__ __nv_bfloat16 g_ctx[BB * NN * DD];
__device__ __nv_bfloat16 g_Wt[3 * 64 * 512];   // [p][n][k] bf16, W transposed (Wf pre-scaled by log2e)
__device__ __nv_bfloat16 g_Wvb[64 * 512];      // Wv bf16, row-major [d][c]

static __device__ __forceinline__ unsigned pack_bf16(float a, float b) {
    __nv_bfloat162 t = __floats2bfloat162_rn(a, b);
    return *reinterpret_cast<unsigned*>(&t);
}
static __device__ __forceinline__ unsigned smem_u32(const void* p) {
    return (unsigned)__cvta_generic_to_shared(p);
}
static __device__ __forceinline__ float ex2f(float x) {
    float y;
    asm("ex2.approx.f32 %0, %1;" : "=f"(y) : "f"(x));
    return y;
}
// non-volatile: register-only op, ptxas may schedule freely
static __device__ __forceinline__ void mma_bf16(float* d, const unsigned* a, const unsigned* b) {
    asm("mma.sync.aligned.m16n8k16.row.col.f32.bf16.bf16.f32 "
        "{%0,%1,%2,%3},{%4,%5,%6,%7},{%8,%9},{%0,%1,%2,%3};\n"
        : "+f"(d[0]), "+f"(d[1]), "+f"(d[2]), "+f"(d[3])
        : "r"(a[0]), "r"(a[1]), "r"(a[2]), "r"(a[3]), "r"(b[0]), "r"(b[1]));
}
static __device__ __forceinline__ void ldsm_x4(unsigned& r0, unsigned& r1, unsigned& r2, unsigned& r3, unsigned addr) {
    asm volatile("ldmatrix.sync.aligned.m8n8.x4.shared.b16 {%0,%1,%2,%3},[%4];\n"
                 : "=r"(r0), "=r"(r1), "=r"(r2), "=r"(r3) : "r"(addr));
}
static __device__ __forceinline__ void ldsm_x4_t(unsigned& r0, unsigned& r1, unsigned& r2, unsigned& r3, unsigned addr) {
    asm volatile("ldmatrix.sync.aligned.m8n8.x4.trans.shared.b16 {%0,%1,%2,%3},[%4];\n"
                 : "=r"(r0), "=r"(r1), "=r"(r2), "=r"(r3) : "r"(addr));
}

#define CP_ASYNC16(dst_u32, src_ptr) \
    asm volatile("cp.async.cg.shared.global [%0],[%1],16;\n" :: "r"(dst_u32), "l"(src_ptr))
#define CP_COMMIT asm volatile("cp.async.commit_group;\n" ::)
#define CP_WAIT0  asm volatile("cp.async.wait_group 0;\n" ::)

// ============================================================
// Kernel 0: weight prep. g_Wt[p][n][k] = W_p[k][n] (Wf scaled by log2e);
// g_Wvb = bf16(Wv)
// ============================================================
__global__ __launch_bounds__(512) void prep_kernel(
    const float* __restrict__ Wf, const float* __restrict__ Wg,
    const float* __restrict__ Wh, const float* __restrict__ Wv)
{
    int idx = blockIdx.x * 512 + threadIdx.x;
    if (idx < 3 * 64 * 512) {
        int p = idx >> 15, n = (idx >> 9) & 63, k = idx & 511;
        const float* W = (p == 0) ? Wf : (p == 1) ? Wg : Wh;
        float v = W[k * 64 + n];
        if (p == 0) v *= LOG2E;
        g_Wt[idx] = __float2bfloat16(v);
    } else {
        int j = idx - 3 * 64 * 512;
        g_Wvb[j] = __float2bfloat16(Wv[j]);
    }
}

// ============================================================
// Kernel 1: projections f,g,h = X @ W* + b*  (f pre-scaled by log2e)
// ============================================================
__global__ __launch_bounds__(384) void proj_kernel(
    const float* __restrict__ x,
    const float* __restrict__ bfv, const float* __restrict__ bgv, const float* __restrict__ bhv)
{
    __shared__ __nv_bfloat16 sX[64][72];
    __shared__ __nv_bfloat16 sW[3][64][72];

    const int b   = blockIdx.y;
    const int n0  = blockIdx.x * 64;
    const int tid = threadIdx.x;
    const int lane = tid & 31, wid = tid >> 5;
    const int p  = wid >> 2;
    const int r0 = (wid & 3) * 16;
    const int l4 = lane >> 2, l2 = lane & 3;

    float acc[8][4];
#pragma unroll
    for (int i = 0; i < 8; i++)
#pragma unroll
        for (int j = 0; j < 4; j++) acc[i][j] = 0.f;

    for (int kc = 0; kc < 8; kc++) {
        for (int idx = tid; idx < 512; idx += 384) {
            int r = idx >> 3, c8 = (idx & 7) << 3;
            const float* src = x + ((size_t)b * NN + n0 + r) * CC + kc * 64 + c8;
            float4 v0 = *reinterpret_cast<const float4*>(src);
            float4 v1 = *reinterpret_cast<const float4*>(src + 4);
            uint4 u;
            u.x = pack_bf16(v0.x, v0.y); u.y = pack_bf16(v0.z, v0.w);
            u.z = pack_bf16(v1.x, v1.y); u.w = pack_bf16(v1.z, v1.w);
            *reinterpret_cast<uint4*>(&sX[r][c8]) = u;
        }
        for (int idx = tid; idx < 1536; idx += 384) {
            int pp = idx >> 9, n = (idx >> 3) & 63, k8 = (idx & 7) << 3;
            uint4 u = *reinterpret_cast<const uint4*>(&g_Wt[((pp * 64 + n) << 9) + kc * 64 + k8]);
            *reinterpret_cast<uint4*>(&sW[pp][n][k8]) = u;
        }
        __syncthreads();

#pragma unroll
        for (int kt = 0; kt < 4; kt++) {
            unsigned a[4];
            ldsm_x4(a[0], a[1], a[2], a[3],
                    smem_u32(&sX[r0 + (lane & 15)][kt * 16 + ((lane >> 4) << 3)]));
#pragma unroll
            for (int nt2 = 0; nt2 < 4; nt2++) {
                unsigned b0, b1, b2, b3;
                int row = nt2 * 16 + (((lane >> 4) & 1) << 3) + (lane & 7);
                int col = kt * 16 + (((lane >> 3) & 1) << 3);
                ldsm_x4(b0, b1, b2, b3, smem_u32(&sW[p][row][col]));
                unsigned bb0[2] = {b0, b1}, bb1[2] = {b2, b3};
                mma_bf16(acc[2 * nt2], a, bb0);
                mma_bf16(acc[2 * nt2 + 1], a, bb1);
            }
        }
        __syncthreads();
    }

    const float* bias = (p == 0) ? bfv : (p == 1) ? bgv : bhv;
    const float bs = (p == 0) ? LOG2E : 1.f;
    __nv_bfloat16* dst = (p == 0) ? g_f : (p == 1) ? g_g : g_h;
#pragma unroll
    for (int nt = 0; nt < 8; nt++) {
        int c0 = nt * 8 + l2 * 2;
        float b0 = bias[c0] * bs, b1 = bias[c0 + 1] * bs;
        int row = n0 + r0 + l4;
        *reinterpret_cast<unsigned*>(&dst[((size_t)b * NN + row    ) * DD + c0]) =
            pack_bf16(acc[nt][0] + b0, acc[nt][1] + b1);
        *reinterpret_cast<unsigned*>(&dst[((size_t)b * NN + row + 8) * DD + c0]) =
            pack_bf16(acc[nt][2] + b0, acc[nt][3] + b1);
    }
}

// ============================================================
// Kernel 2: flash attention, no max, exp2 path, 128-key tiles.
// 4 warps x 32 q-rows each (two A-fragment sets per warp) ->
// each K/H LDSM fragment feeds 4 mmas => smem traffic per mma halved.
// 128 threads, grid (32, 8).
// ============================================================
__global__ __launch_bounds__(128) void attn_kernel(const float* __restrict__ gamma_p)
{
    extern __shared__ __align__(16) char smem_raw[];
    __nv_bfloat16* sQ = reinterpret_cast<__nv_bfloat16*>(smem_raw);   // [128][72]
    __nv_bfloat16* sK = sQ + 128 * 72;                                 // [2][128][72]
    __nv_bfloat16* sH = sK + 2 * 128 * 72;                             // [2][128][72]

    const int b  = blockIdx.y;
    const int q0 = blockIdx.x * 128;
    const int tid = threadIdx.x, lane = tid & 31, w = tid >> 5;   // w in 0..3
    const int l4 = lane >> 2, l2 = lane & 3;
    const int r0lo = w * 32;
    const int r0hi = w * 32 + 16;

    // prefetch K/H tile 0 (128 keys x 64 d each): 2048 chunks of 16B
    for (int idx = tid; idx < 2048; idx += 128) {
        int which = idx >> 10, r = (idx >> 3) & 127, c8 = (idx & 7) << 3;
        const __nv_bfloat16* src = (which ? g_h : g_g) + ((size_t)b * NN + r) * DD + c8;
        __nv_bfloat16* dst = (which ? sH : sK) + r * 72 + c8;
        CP_ASYNC16(smem_u32(dst), src);
    }
    CP_COMMIT;

    // Q tile (128 rows x 64 d)
    for (int idx = tid; idx < 1024; idx += 128) {
        int r = idx >> 3, c8 = (idx & 7) << 3;
        *reinterpret_cast<uint4*>(sQ + r * 72 + c8) =
            *reinterpret_cast<const uint4*>(&g_f[((size_t)b * NN + q0 + r) * DD + c8]);
    }
    __syncthreads();

    unsigned qlo[4][4], qhi[4][4];
#pragma unroll
    for (int kt = 0; kt < 4; kt++) {
        ldsm_x4(qlo[kt][0], qlo[kt][1], qlo[kt][2], qlo[kt][3],
                smem_u32(sQ + (r0lo + (lane & 15)) * 72 + kt * 16 + ((lane >> 4) << 3)));
        ldsm_x4(qhi[kt][0], qhi[kt][1], qhi[kt][2], qhi[kt][3],
                smem_u32(sQ + (r0hi + (lane & 15)) * 72 + kt * 16 + ((lane >> 4) << 3)));
    }

    float llo0 = 0.f, llo1 = 0.f, lhi0 = 0.f, lhi1 = 0.f;
    float olo[8][4], ohi[8][4];
#pragma unroll
    for (int i = 0; i < 8; i++)
#pragma unroll
        for (int j = 0; j < 4; j++) { olo[i][j] = 0.f; ohi[i][j] = 0.f; }

    for (int t = 0; t < 32; t++) {
        const int buf = t & 1;
        CP_WAIT0;
        __syncthreads();

        if (t + 1 < 32) {
            int nb = (t + 1) & 1;
            for (int idx = tid; idx < 2048; idx += 128) {
                int which = idx >> 10, r = (idx >> 3) & 127, c8 = (idx & 7) << 3;
                const __nv_bfloat16* src =
                    (which ? g_h : g_g) + ((size_t)b * NN + (t + 1) * 128 + r) * DD + c8;
                __nv_bfloat16* dst = (which ? sH : sK) + (nb * 128 + r) * 72 + c8;
                CP_ASYNC16(smem_u32(dst), src);
            }
            CP_COMMIT;
        }

        const __nv_bfloat16* Kb = sK + buf * 128 * 72;
        const __nv_bfloat16* Hb = sH + buf * 128 * 72;

#pragma unroll
        for (int kb = 0; kb < 8; kb++) {
            // ---- S for both q halves: each K fragment feeds 4 mmas ----
            float slo[8], shi[8];
#pragma unroll
            for (int j = 0; j < 8; j++) { slo[j] = 0.f; shi[j] = 0.f; }

#pragma unroll
            for (int kt = 0; kt < 4; kt++) {
                unsigned b0, b1, b2, b3;
                int row = kb * 16 + (((lane >> 4) & 1) << 3) + (lane & 7);
                int col = kt * 16 + (((lane >> 3) & 1) << 3);
                ldsm_x4(b0, b1, b2, b3, smem_u32(Kb + row * 72 + col));
                unsigned bb0[2] = {b0, b1}, bb1[2] = {b2, b3};
                mma_bf16(slo, qlo[kt], bb0);
                mma_bf16(slo + 4, qlo[kt], bb1);
                mma_bf16(shi, qhi[kt], bb0);
                mma_bf16(shi + 4, qhi[kt], bb1);
            }

            // ---- H fragments (shared by both PV halves) ----
            unsigned hb[4][4];
#pragma unroll
            for (int nt2 = 0; nt2 < 4; nt2++) {
                int row = kb * 16 + (((lane >> 3) & 1) << 3) + (lane & 7);
                int col = nt2 * 16 + ((lane >> 4) << 3);
                ldsm_x4_t(hb[nt2][0], hb[nt2][1], hb[nt2][2], hb[nt2][3],
                          smem_u32(Hb + row * 72 + col));
            }

            // ---- exp2 + partial sums + pack, lo ----
            float a0 = ex2f(slo[0]), a1 = ex2f(slo[1]), a2 = ex2f(slo[2]), a3 = ex2f(slo[3]);
            float a4 = ex2f(slo[4]), a5 = ex2f(slo[5]), a6 = ex2f(slo[6]), a7 = ex2f(slo[7]);
            llo0 += a0 + a1 + a4 + a5;
            llo1 += a2 + a3 + a6 + a7;
            unsigned plo[4];
            plo[0] = pack_bf16(a0, a1); plo[1] = pack_bf16(a2, a3);
            plo[2] = pack_bf16(a4, a5); plo[3] = pack_bf16(a6, a7);

            // ---- exp2 + partial sums + pack, hi ----
            float c0 = ex2f(shi[0]), c1 = ex2f(shi[1]), c2 = ex2f(shi[2]), c3 = ex2f(shi[3]);
            float c4 = ex2f(shi[4]), c5 = ex2f(shi[5]), c6 = ex2f(shi[6]), c7 = ex2f(shi[7]);
            lhi0 += c0 + c1 + c4 + c5;
            lhi1 += c2 + c3 + c6 + c7;
            unsigned phi[4];
            phi[0] = pack_bf16(c0, c1); phi[1] = pack_bf16(c2, c3);
            phi[2] = pack_bf16(c4, c5); phi[3] = pack_bf16(c6, c7);

            // ---- PV both halves (H fragments reused) ----
#pragma unroll
            for (int nt2 = 0; nt2 < 4; nt2++) {
                unsigned bb0[2] = {hb[nt2][0], hb[nt2][1]};
                unsigned bb1[2] = {hb[nt2][2], hb[nt2][3]};
                mma_bf16(olo[2 * nt2], plo, bb0);
                mma_bf16(olo[2 * nt2 + 1], plo, bb1);
                mma_bf16(ohi[2 * nt2], phi, bb0);
                mma_bf16(ohi[2 * nt2 + 1], phi, bb1);
            }
        }
    }

    llo0 += __shfl_xor_sync(0xffffffffu, llo0, 1);
    llo0 += __shfl_xor_sync(0xffffffffu, llo0, 2);
    llo1 += __shfl_xor_sync(0xffffffffu, llo1, 1);
    llo1 += __shfl_xor_sync(0xffffffffu, llo1, 2);
    lhi0 += __shfl_xor_sync(0xffffffffu, lhi0, 1);
    lhi0 += __shfl_xor_sync(0xffffffffu, lhi0, 2);
    lhi1 += __shfl_xor_sync(0xffffffffu, lhi1, 1);
    lhi1 += __shfl_xor_sync(0xffffffffu, lhi1, 2);

    float gm = *gamma_p;
    float slo0 = gm / llo0, slo1 = gm / llo1;
    float shi0 = gm / lhi0, shi1 = gm / lhi1;
#pragma unroll
    for (int nt = 0; nt < 8; nt++) {
        int c0 = nt * 8 + l2 * 2;
        int rlo = q0 + r0lo + l4;
        int rhi = q0 + r0hi + l4;
        *reinterpret_cast<unsigned*>(&g_ctx[((size_t)b * NN + rlo    ) * DD + c0]) =
            pack_bf16(olo[nt][0] * slo0, olo[nt][1] * slo0);
        *reinterpret_cast<unsigned*>(&g_ctx[((size_t)b * NN + rlo + 8) * DD + c0]) =
            pack_bf16(olo[nt][2] * slo1, olo[nt][3] * slo1);
        *reinterpret_cast<unsigned*>(&g_ctx[((size_t)b * NN + rhi    ) * DD + c0]) =
            pack_bf16(ohi[nt][0] * shi0, ohi[nt][1] * shi0);
        *reinterpret_cast<unsigned*>(&g_ctx[((size_t)b * NN + rhi + 8) * DD + c0]) =
            pack_bf16(ohi[nt][2] * shi1, ohi[nt][3] * shi1);
    }
}

// ============================================================
// Kernel 3: out = ctx @ Wv + bv + x  (unchanged, 33.7us known)
// ============================================================
#define WVP 264
__global__ __launch_bounds__(512, 2) void epi_kernel(
    const float* __restrict__ x,
    const float* __restrict__ bv, float* __restrict__ out)
{
    extern __shared__ __align__(16) char smem_raw[];
    __nv_bfloat16* sCtx = reinterpret_cast<__nv_bfloat16*>(smem_raw);   // [64][72]
    __nv_bfloat16* sWv  = sCtx + 64 * 72;                                // [64][264]

    const int b    = blockIdx.z;
    const int n0   = blockIdx.x * 64;
    const int ch0  = blockIdx.y * 256;
    const int tid = threadIdx.x, lane = tid & 31, w = tid >> 5;
    const int l4 = lane >> 2, l2 = lane & 3;
    const int r0 = (w & 3) * 16;
    const int c0 = (w >> 2) * 64;

    for (int idx = tid; idx < 2048; idx += 512) {
        int r = idx >> 5, c8 = (idx & 31) << 3;
        CP_ASYNC16(smem_u32(sWv + r * WVP + c8), g_Wvb + (r << 9) + ch0 + c8);
    }
    for (int idx = tid; idx < 512; idx += 512) {
        int r = idx >> 3, c8 = (idx & 7) << 3;
        CP_ASYNC16(smem_u32(sCtx + r * 72 + c8), &g_ctx[((size_t)b * NN + n0 + r) * DD + c8]);
    }
    CP_COMMIT;
    CP_WAIT0;
    __syncthreads();

    float acc[8][4];
#pragma unroll
    for (int i = 0; i < 8; i++)
#pragma unroll
        for (int j = 0; j < 4; j++) acc[i][j] = 0.f;

#pragma unroll
    for (int kt = 0; kt < 4; kt++) {
        unsigned a[4];
        ldsm_x4(a[0], a[1], a[2], a[3],
                smem_u32(sCtx + (r0 + (lane & 15)) * 72 + kt * 16 + ((lane >> 4) << 3)));
#pragma unroll
        for (int nt2 = 0; nt2 < 4; nt2++) {
            unsigned b0, b1, b2, b3;
            int row = kt * 16 + (((lane >> 3) & 1) << 3) + (lane & 7);
            int col = c0 + nt2 * 16 + ((lane >> 4) << 3);
            ldsm_x4_t(b0, b1, b2, b3, smem_u32(sWv + row * WVP + col));
            unsigned bb0[2] = {b0, b1}, bb1[2] = {b2, b3};
            mma_bf16(acc[2 * nt2], a, bb0);
            mma_bf16(acc[2 * nt2 + 1], a, bb1);
        }
    }

#pragma unroll
    for (int nt = 0; nt < 8; nt++) {
        int col = ch0 + c0 + nt * 8 + l2 * 2;
        float2 bvv = *reinterpret_cast<const float2*>(&bv[col]);
        size_t off0 = ((size_t)b * NN + n0 + r0 + l4    ) * CC + col;
        size_t off1 = ((size_t)b * NN + n0 + r0 + l4 + 8) * CC + col;
        float2 x0 = *reinterpret_cast<const float2*>(&x[off0]);
        float2 x1 = *reinterpret_cast<const float2*>(&x[off1]);
        float2 o0 = make_float2(acc[nt][0] + bvv.x + x0.x, acc[nt][1] + bvv.y + x0.y);
        float2 o1 = make_float2(acc[nt][2] + bvv.x + x1.x, acc[nt][3] + bvv.y + x1.y);
        *reinterpret_cast<float2*>(&out[off0]) = o0;
        *reinterpret_cast<float2*>(&out[off1]) = o1;
    }
}

// ============================================================
extern "C" void kernel_launch(void* const* d_in, const int* in_sizes, int n_in,
                              void* d_out, int out_size)
{
    const float* x     = (const float*)d_in[0];
    const float* Wf    = (const float*)d_in[1];
    const float* bf    = (const float*)d_in[2];
    const float* Wg    = (const float*)d_in[3];
    const float* bg    = (const float*)d_in[4];
    const float* Wh    = (const float*)d_in[5];
    const float* bh    = (const float*)d_in[6];
    const float* Wv    = (const float*)d_in[7];
    const float* bv    = (const float*)d_in[8];
    const float* gamma = (const float*)d_in[9];
    float* out = (float*)d_out;

    const int attn_smem = (128 * 72 + 2 * 128 * 72 + 2 * 128 * 72) * 2;  // 92160
    const int epi_smem  = (64 * 72 + 64 * WVP) * 2;                      // 43008
    cudaFuncSetAttribute(attn_kernel, cudaFuncAttributeMaxDynamicSharedMemorySize, attn_smem);
    cudaFuncSetAttribute(epi_kernel,  cudaFuncAttributeMaxDynamicSharedMemorySize, epi_smem);

    prep_kernel<<<256, 512>>>(Wf, Wg, Wh, Wv);
    proj_kernel<<<dim3(NN / 64, BB), 384>>>(x, bf, bg, bh);
    attn_kernel<<<dim3(NN / 128, BB), 128, attn_smem>>>(gamma);
    epi_kernel<<<dim3(NN / 64, 2, BB), 512, epi_smem>>>(x, bv, out);
}

// round 9
// speedup vs baseline: 1.0865x; 1.0865x over previous
#include <cuda_runtime.h>
#include <cuda_bf16.h>
#include <math.h>
#include <stdint.h>

#define BB 8
#define NN 4096
#define CC 512
#define DD 64
#define LOG2E 1.4426950408889634f

// Scratch (allocation-free: __device__ globals)
__device__ __nv_bfloat16 g_f[BB * NN * DD];
__device__ __nv_bfloat16 g_g[BB * NN * DD];
__device__ __nv_bfloat16 g_h[BB * NN * DD];
__device__ __nv_bfloat16 g_ctx[BB * NN * DD];
__device__ __nv_bfloat16 g_Wt[3 * 64 * 512];   // [p][n][k] bf16, W transposed (Wf pre-scaled by log2e)
__device__ __nv_bfloat16 g_Wvb[64 * 512];      // Wv bf16, row-major [d][c]

static __device__ __forceinline__ unsigned pack_bf16(float a, float b) {
    __nv_bfloat162 t = __floats2bfloat162_rn(a, b);
    return *reinterpret_cast<unsigned*>(&t);
}
static __device__ __forceinline__ unsigned smem_u32(const void* p) {
    return (unsigned)__cvta_generic_to_shared(p);
}
static __device__ __forceinline__ float ex2f(float x) {
    float y;
    asm("ex2.approx.f32 %0, %1;" : "=f"(y) : "f"(x));
    return y;
}
// non-volatile: register-only op, ptxas may schedule freely
static __device__ __forceinline__ void mma_bf16(float* d, const unsigned* a, const unsigned* b) {
    asm("mma.sync.aligned.m16n8k16.row.col.f32.bf16.bf16.f32 "
        "{%0,%1,%2,%3},{%4,%5,%6,%7},{%8,%9},{%0,%1,%2,%3};\n"
        : "+f"(d[0]), "+f"(d[1]), "+f"(d[2]), "+f"(d[3])
        : "r"(a[0]), "r"(a[1]), "r"(a[2]), "r"(a[3]), "r"(b[0]), "r"(b[1]));
}
static __device__ __forceinline__ void ldsm_x4(unsigned& r0, unsigned& r1, unsigned& r2, unsigned& r3, unsigned addr) {
    asm volatile("ldmatrix.sync.aligned.m8n8.x4.shared.b16 {%0,%1,%2,%3},[%4];\n"
                 : "=r"(r0), "=r"(r1), "=r"(r2), "=r"(r3) : "r"(addr));
}
static __device__ __forceinline__ void ldsm_x4_t(unsigned& r0, unsigned& r1, unsigned& r2, unsigned& r3, unsigned addr) {
    asm volatile("ldmatrix.sync.aligned.m8n8.x4.trans.shared.b16 {%0,%1,%2,%3},[%4];\n"
                 : "=r"(r0), "=r"(r1), "=r"(r2), "=r"(r3) : "r"(addr));
}

#define CP_ASYNC16(dst_u32, src_ptr) \
    asm volatile("cp.async.cg.shared.global [%0],[%1],16;\n" :: "r"(dst_u32), "l"(src_ptr))
#define CP_COMMIT asm volatile("cp.async.commit_group;\n" ::)
#define CP_WAIT0  asm volatile("cp.async.wait_group 0;\n" ::)
#define CP_WAIT1  asm volatile("cp.async.wait_group 1;\n" ::)

// ============================================================
// Kernel 0: weight prep. g_Wt[p][n][k] = W_p[k][n] (Wf scaled by log2e);
// g_Wvb = bf16(Wv)
// ============================================================
__global__ __launch_bounds__(512) void prep_kernel(
    const float* __restrict__ Wf, const float* __restrict__ Wg,
    const float* __restrict__ Wh, const float* __restrict__ Wv)
{
    int idx = blockIdx.x * 512 + threadIdx.x;
    if (idx < 3 * 64 * 512) {
        int p = idx >> 15, n = (idx >> 9) & 63, k = idx & 511;
        const float* W = (p == 0) ? Wf : (p == 1) ? Wg : Wh;
        float v = W[k * 64 + n];
        if (p == 0) v *= LOG2E;
        g_Wt[idx] = __float2bfloat16(v);
    } else {
        int j = idx - 3 * 64 * 512;
        g_Wvb[j] = __float2bfloat16(Wv[j]);
    }
}

// ============================================================
// Kernel 1: projections f,g,h = X @ W* + b*  — DOUBLE-BUFFERED:
// cp.async for W (bf16, no conversion), X convert+STS into idle buffer,
// staging overlaps mma. grid (64, 8), 384 threads.
// ============================================================
#define PX 72
__global__ __launch_bounds__(384) void proj_kernel(
    const float* __restrict__ x,
    const float* __restrict__ bfv, const float* __restrict__ bgv, const float* __restrict__ bhv)
{
    extern __shared__ __align__(16) char smem_raw[];
    __nv_bfloat16* sX = reinterpret_cast<__nv_bfloat16*>(smem_raw); // [2][64][PX]
    __nv_bfloat16* sW = sX + 2 * 64 * PX;                            // [2][3][64][PX]

    const int b   = blockIdx.y;
    const int n0  = blockIdx.x * 64;
    const int tid = threadIdx.x;
    const int lane = tid & 31, wid = tid >> 5;
    const int p  = wid >> 2;
    const int r0 = (wid & 3) * 16;
    const int l4 = lane >> 2, l2 = lane & 3;

    float acc[8][4];
#pragma unroll
    for (int i = 0; i < 8; i++)
#pragma unroll
        for (int j = 0; j < 4; j++) acc[i][j] = 0.f;

#define STAGE_X(kc, bufi)                                                           \
    for (int idx = tid; idx < 512; idx += 384) {                                    \
        int r = idx >> 3, c8 = (idx & 7) << 3;                                      \
        const float* src = x + ((size_t)b * NN + n0 + r) * CC + (kc) * 64 + c8;     \
        float4 v0 = *reinterpret_cast<const float4*>(src);                          \
        float4 v1 = *reinterpret_cast<const float4*>(src + 4);                      \
        uint4 u;                                                                    \
        u.x = pack_bf16(v0.x, v0.y); u.y = pack_bf16(v0.z, v0.w);                   \
        u.z = pack_bf16(v1.x, v1.y); u.w = pack_bf16(v1.z, v1.w);                   \
        *reinterpret_cast<uint4*>(sX + ((bufi) * 64 + r) * PX + c8) = u;            \
    }

#define STAGE_W(kc, bufi)                                                           \
    for (int idx = tid; idx < 1536; idx += 384) {                                   \
        int pp = idx >> 9, n = (idx >> 3) & 63, k8 = (idx & 7) << 3;                \
        CP_ASYNC16(smem_u32(sW + (((bufi) * 3 + pp) * 64 + n) * PX + k8),           \
                   g_Wt + ((pp * 64 + n) << 9) + (kc) * 64 + k8);                   \
    }                                                                               \
    CP_COMMIT;

    STAGE_X(0, 0);
    STAGE_W(0, 0);

    for (int kc = 0; kc < 8; kc++) {
        const int buf = kc & 1;
        if (kc < 7) {
            STAGE_X(kc + 1, buf ^ 1);
            STAGE_W(kc + 1, buf ^ 1);
            CP_WAIT1;
        } else {
            CP_WAIT0;
        }
        __syncthreads();   // W(kc) arrived + X(kc) STS visible

        const __nv_bfloat16* Xb = sX + buf * 64 * PX;
        const __nv_bfloat16* Wb = sW + (buf * 3 + p) * 64 * PX;

#pragma unroll
        for (int kt = 0; kt < 4; kt++) {
            unsigned a[4];
            ldsm_x4(a[0], a[1], a[2], a[3],
                    smem_u32(Xb + (r0 + (lane & 15)) * PX + kt * 16 + ((lane >> 4) << 3)));
#pragma unroll
            for (int nt2 = 0; nt2 < 4; nt2++) {
                unsigned b0, b1, b2, b3;
                int row = nt2 * 16 + (((lane >> 4) & 1) << 3) + (lane & 7);
                int col = kt * 16 + (((lane >> 3) & 1) << 3);
                ldsm_x4(b0, b1, b2, b3, smem_u32(Wb + row * PX + col));
                unsigned bb0[2] = {b0, b1}, bb1[2] = {b2, b3};
                mma_bf16(acc[2 * nt2], a, bb0);
                mma_bf16(acc[2 * nt2 + 1], a, bb1);
            }
        }
        __syncthreads();   // all warps done reading buf before it is overwritten
    }

    const float* bias = (p == 0) ? bfv : (p == 1) ? bgv : bhv;
    const float bs = (p == 0) ? LOG2E : 1.f;
    __nv_bfloat16* dst = (p == 0) ? g_f : (p == 1) ? g_g : g_h;
#pragma unroll
    for (int nt = 0; nt < 8; nt++) {
        int c0 = nt * 8 + l2 * 2;
        float b0 = bias[c0] * bs, b1 = bias[c0 + 1] * bs;
        int row = n0 + r0 + l4;
        *reinterpret_cast<unsigned*>(&dst[((size_t)b * NN + row    ) * DD + c0]) =
            pack_bf16(acc[nt][0] + b0, acc[nt][1] + b1);
        *reinterpret_cast<unsigned*>(&dst[((size_t)b * NN + row + 8) * DD + c0]) =
            pack_bf16(acc[nt][2] + b0, acc[nt][3] + b1);
    }
}

// ============================================================
// Kernel 2: flash attention (R7 version — best: 204.8 total).
// no max, exp2 path, 128-key tiles, S(kb+1) pipelined ahead.
// 8 warps x 16 q-rows, 256 threads, grid (32, 8).
// ============================================================
#define ISSUE_S(kb, sc, Kb)                                                          \
    do {                                                                             \
        _Pragma("unroll")                                                            \
        for (int j = 0; j < 8; j++) (sc)[j] = 0.f;                                   \
        _Pragma("unroll")                                                            \
        for (int kt = 0; kt < 4; kt++) {                                             \
            unsigned b0, b1, b2, b3;                                                 \
            int row = (kb) * 16 + (((lane >> 4) & 1) << 3) + (lane & 7);             \
            int col = kt * 16 + (((lane >> 3) & 1) << 3);                            \
            ldsm_x4(b0, b1, b2, b3, smem_u32((Kb) + row * 72 + col));                \
            unsigned bb0[2] = {b0, b1}, bb1[2] = {b2, b3};                           \
            mma_bf16((sc), qa[kt], bb0);                                             \
            mma_bf16((sc) + 4, qa[kt], bb1);                                         \
        }                                                                            \
    } while (0)

__global__ __launch_bounds__(256, 2) void attn_kernel(const float* __restrict__ gamma_p)
{
    extern __shared__ __align__(16) char smem_raw[];
    __nv_bfloat16* sQ = reinterpret_cast<__nv_bfloat16*>(smem_raw);   // [128][72]
    __nv_bfloat16* sK = sQ + 128 * 72;                                 // [2][128][72]
    __nv_bfloat16* sH = sK + 2 * 128 * 72;                             // [2][128][72]

    const int b  = blockIdx.y;
    const int q0 = blockIdx.x * 128;
    const int tid = threadIdx.x, lane = tid & 31, w = tid >> 5;
    const int l4 = lane >> 2, l2 = lane & 3;
    const int r0 = w * 16;

    for (int idx = tid; idx < 2048; idx += 256) {
        int which = idx >> 10, r = (idx >> 3) & 127, c8 = (idx & 7) << 3;
        const __nv_bfloat16* src = (which ? g_h : g_g) + ((size_t)b * NN + r) * DD + c8;
        __nv_bfloat16* dst = (which ? sH : sK) + r * 72 + c8;
        CP_ASYNC16(smem_u32(dst), src);
    }
    CP_COMMIT;

    for (int idx = tid; idx < 1024; idx += 256) {
        int r = idx >> 3, c8 = (idx & 7) << 3;
        *reinterpret_cast<uint4*>(sQ + r * 72 + c8) =
            *reinterpret_cast<const uint4*>(&g_f[((size_t)b * NN + q0 + r) * DD + c8]);
    }
    __syncthreads();

    unsigned qa[4][4];
#pragma unroll
    for (int kt = 0; kt < 4; kt++)
        ldsm_x4(qa[kt][0], qa[kt][1], qa[kt][2], qa[kt][3],
                smem_u32(sQ + (r0 + (lane & 15)) * 72 + kt * 16 + ((lane >> 4) << 3)));

    float l0 = 0.f, l1 = 0.f;
    float oacc[8][4];
#pragma unroll
    for (int i = 0; i < 8; i++)
#pragma unroll
        for (int j = 0; j < 4; j++) oacc[i][j] = 0.f;

    for (int t = 0; t < 32; t++) {
        const int buf = t & 1;
        CP_WAIT0;
        __syncthreads();

        if (t + 1 < 32) {
            int nb = (t + 1) & 1;
            for (int idx = tid; idx < 2048; idx += 256) {
                int which = idx >> 10, r = (idx >> 3) & 127, c8 = (idx & 7) << 3;
                const __nv_bfloat16* src =
                    (which ? g_h : g_g) + ((size_t)b * NN + (t + 1) * 128 + r) * DD + c8;
                __nv_bfloat16* dst = (which ? sH : sK) + (nb * 128 + r) * 72 + c8;
                CP_ASYNC16(smem_u32(dst), src);
            }
            CP_COMMIT;
        }

        const __nv_bfloat16* Kb = sK + buf * 128 * 72;
        const __nv_bfloat16* Hb = sH + buf * 128 * 72;

        float scA[8], scB[8];
        ISSUE_S(0, scA, Kb);

#pragma unroll
        for (int kb = 0; kb < 8; kb++) {
            float* cur = (kb & 1) ? scB : scA;
            float* nxt = (kb & 1) ? scA : scB;

            if (kb < 7) ISSUE_S(kb + 1, nxt, Kb);

            unsigned hb[4][4];
#pragma unroll
            for (int nt2 = 0; nt2 < 4; nt2++) {
                int row = kb * 16 + (((lane >> 3) & 1) << 3) + (lane & 7);
                int col = nt2 * 16 + ((lane >> 4) << 3);
                ldsm_x4_t(hb[nt2][0], hb[nt2][1], hb[nt2][2], hb[nt2][3],
                          smem_u32(Hb + row * 72 + col));
            }

            float e0 = ex2f(cur[0]), e1 = ex2f(cur[1]);
            float e2 = ex2f(cur[2]), e3 = ex2f(cur[3]);
            float e4 = ex2f(cur[4]), e5 = ex2f(cur[5]);
            float e6 = ex2f(cur[6]), e7 = ex2f(cur[7]);
            l0 += e0 + e1 + e4 + e5;
            l1 += e2 + e3 + e6 + e7;

            unsigned pa[4];
            pa[0] = pack_bf16(e0, e1);
            pa[1] = pack_bf16(e2, e3);
            pa[2] = pack_bf16(e4, e5);
            pa[3] = pack_bf16(e6, e7);

#pragma unroll
            for (int nt2 = 0; nt2 < 4; nt2++) {
                unsigned bb0[2] = {hb[nt2][0], hb[nt2][1]};
                unsigned bb1[2] = {hb[nt2][2], hb[nt2][3]};
                mma_bf16(oacc[2 * nt2], pa, bb0);
                mma_bf16(oacc[2 * nt2 + 1], pa, bb1);
            }
        }
    }

    l0 += __shfl_xor_sync(0xffffffffu, l0, 1);
    l0 += __shfl_xor_sync(0xffffffffu, l0, 2);
    l1 += __shfl_xor_sync(0xffffffffu, l1, 1);
    l1 += __shfl_xor_sync(0xffffffffu, l1, 2);

    float gm = *gamma_p;
    float s0 = gm / l0, s1 = gm / l1;
#pragma unroll
    for (int nt = 0; nt < 8; nt++) {
        int c0 = nt * 8 + l2 * 2;
        int row = q0 + r0 + l4;
        *reinterpret_cast<unsigned*>(&g_ctx[((size_t)b * NN + row    ) * DD + c0]) =
            pack_bf16(oacc[nt][0] * s0, oacc[nt][1] * s0);
        *reinterpret_cast<unsigned*>(&g_ctx[((size_t)b * NN + row + 8) * DD + c0]) =
            pack_bf16(oacc[nt][2] * s1, oacc[nt][3] * s1);
    }
}

// ============================================================
// Kernel 3: out = ctx @ Wv + bv + x — acc restaged to smem (bf16),
// then fully-coalesced float4 x-load / out-store pass.
// grid (64, 2, 8), 512 threads.
// ============================================================
#define WVP 264
__global__ __launch_bounds__(512, 2) void epi_kernel(
    const float* __restrict__ x,
    const float* __restrict__ bv, float* __restrict__ out)
{
    extern __shared__ __align__(16) char smem_raw[];
    __nv_bfloat16* sCtx = reinterpret_cast<__nv_bfloat16*>(smem_raw);   // [64][72]
    __nv_bfloat16* sWv  = sCtx + 64 * 72;                                // [64][264] (reused as result stage)

    const int b    = blockIdx.z;
    const int n0   = blockIdx.x * 64;
    const int ch0  = blockIdx.y * 256;
    const int tid = threadIdx.x, lane = tid & 31, w = tid >> 5;
    const int l4 = lane >> 2, l2 = lane & 3;
    const int r0 = (w & 3) * 16;
    const int c0 = (w >> 2) * 64;

    for (int idx = tid; idx < 2048; idx += 512) {
        int r = idx >> 5, c8 = (idx & 31) << 3;
        CP_ASYNC16(smem_u32(sWv + r * WVP + c8), g_Wvb + (r << 9) + ch0 + c8);
    }
    for (int idx = tid; idx < 512; idx += 512) {
        int r = idx >> 3, c8 = (idx & 7) << 3;
        CP_ASYNC16(smem_u32(sCtx + r * 72 + c8), &g_ctx[((size_t)b * NN + n0 + r) * DD + c8]);
    }
    CP_COMMIT;
    CP_WAIT0;
    __syncthreads();

    float acc[8][4];
#pragma unroll
    for (int i = 0; i < 8; i++)
#pragma unroll
        for (int j = 0; j < 4; j++) acc[i][j] = 0.f;

#pragma unroll
    for (int kt = 0; kt < 4; kt++) {
        unsigned a[4];
        ldsm_x4(a[0], a[1], a[2], a[3],
                smem_u32(sCtx + (r0 + (lane & 15)) * 72 + kt * 16 + ((lane >> 4) << 3)));
#pragma unroll
        for (int nt2 = 0; nt2 < 4; nt2++) {
            unsigned b0, b1, b2, b3;
            int row = kt * 16 + (((lane >> 3) & 1) << 3) + (lane & 7);
            int col = c0 + nt2 * 16 + ((lane >> 4) << 3);
            ldsm_x4_t(b0, b1, b2, b3, smem_u32(sWv + row * WVP + col));
            unsigned bb0[2] = {b0, b1}, bb1[2] = {b2, b3};
            mma_bf16(acc[2 * nt2], a, bb0);
            mma_bf16(acc[2 * nt2 + 1], a, bb1);
        }
    }

    // restage acc into sWv (done being read) as bf16
    __syncthreads();
#pragma unroll
    for (int nt = 0; nt < 8; nt++) {
        int col = c0 + nt * 8 + l2 * 2;
        *reinterpret_cast<unsigned*>(sWv + (r0 + l4    ) * WVP + col) =
            pack_bf16(acc[nt][0], acc[nt][1]);
        *reinterpret_cast<unsigned*>(sWv + (r0 + l4 + 8) * WVP + col) =
            pack_bf16(acc[nt][2], acc[nt][3]);
    }
    __syncthreads();

    // coalesced output pass: 4096 float4 tasks over [64 rows][256 cols]
    for (int idx = tid; idx < 4096; idx += 512) {
        int row = idx >> 6, c4 = (idx & 63) << 2;
        __nv_bfloat162 v01 = *reinterpret_cast<const __nv_bfloat162*>(sWv + row * WVP + c4);
        __nv_bfloat162 v23 = *reinterpret_cast<const __nv_bfloat162*>(sWv + row * WVP + c4 + 2);
        float4 bvv = *reinterpret_cast<const float4*>(bv + ch0 + c4);
        size_t off = ((size_t)b * NN + n0 + row) * CC + ch0 + c4;
        float4 xx = *reinterpret_cast<const float4*>(x + off);
        float4 o;
        o.x = __bfloat162float(v01.x) + bvv.x + xx.x;
        o.y = __bfloat162float(v01.y) + bvv.y + xx.y;
        o.z = __bfloat162float(v23.x) + bvv.z + xx.z;
        o.w = __bfloat162float(v23.y) + bvv.w + xx.w;
        *reinterpret_cast<float4*>(out + off) = o;
    }
}

// ============================================================
extern "C" void kernel_launch(void* const* d_in, const int* in_sizes, int n_in,
                              void* d_out, int out_size)
{
    const float* x     = (const float*)d_in[0];
    const float* Wf    = (const float*)d_in[1];
    const float* bf    = (const float*)d_in[2];
    const float* Wg    = (const float*)d_in[3];
    const float* bg    = (const float*)d_in[4];
    const float* Wh    = (const float*)d_in[5];
    const float* bh    = (const float*)d_in[6];
    const float* Wv    = (const float*)d_in[7];
    const float* bv    = (const float*)d_in[8];
    const float* gamma = (const float*)d_in[9];
    float* out = (float*)d_out;

    const int proj_smem = (2 * 64 * PX + 2 * 3 * 64 * PX) * 2;          // 73728
    const int attn_smem = (128 * 72 + 2 * 128 * 72 + 2 * 128 * 72) * 2; // 92160
    const int epi_smem  = (64 * 72 + 64 * WVP) * 2;                     // 43008
    cudaFuncSetAttribute(proj_kernel, cudaFuncAttributeMaxDynamicSharedMemorySize, proj_smem);
    cudaFuncSetAttribute(attn_kernel, cudaFuncAttributeMaxDynamicSharedMemorySize, attn_smem);
    cudaFuncSetAttribute(epi_kernel,  cudaFuncAttributeMaxDynamicSharedMemorySize, epi_smem);

    prep_kernel<<<256, 512>>>(Wf, Wg, Wh, Wv);
    proj_kernel<<<dim3(NN / 64, BB), 384, proj_smem>>>(x, bf, bg, bh);
    attn_kernel<<<dim3(NN / 128, BB), 256, attn_smem>>>(gamma);
    epi_kernel<<<dim3(NN / 64, 2, BB), 512, epi_smem>>>(x, bv, out);
}